// round 9
// baseline (speedup 1.0000x reference)
#include <cuda_runtime.h>
#include <cstdint>

// soft_to_hard_quantize via tensor cores (tf32 mma.sync, 3-term split).
// R9: TWO 16-vector tiles per warp — every codebook B-fragment LDS feeds the
// MMAs of both tiles, halving smem crossbar traffic per vector (L1 was the
// 73.7% binder in R8). Fragment mappings identical to the verified R8 kernel.
//
// logit[v][m] = 14.4269504*dot(x_v, r_m) - 7.2134752*||r_m||^2   (log2 domain)
// e = exp2(logit - rowmax);  z_v = sum_m e*r_m / sum_m e

#define TPB   128   // 4 warps/block, 2 tiles (32 vectors) per warp
#define DVEC  16

__device__ float4 gP1[512];   // [s(2)][m(64)][q(4)] : {h(k=8s+q), h(8s+q+4), l, l} of 14.43*r[m]
__device__ float4 gPB[512];   // [s(8)][j(16)][q(4)] : {h(r[8s+2q][j]), h(r[8s+2q+1][j]), l, l}
__device__ float2 gB2[32];    // [t(8)][q(4)]        : {b2[8t+2q], b2[8t+2q+1]}

__device__ __forceinline__ uint32_t tf32h(float x) {
    uint32_t h; asm("cvt.rna.tf32.f32 %0, %1;" : "=r"(h) : "f"(x)); return h;
}
__device__ __forceinline__ float uf(uint32_t u) { return __uint_as_float(u); }
__device__ __forceinline__ float ex2f(float x) {
    float r; asm("ex2.approx.ftz.f32 %0, %1;" : "=f"(r) : "f"(x)); return r;
}
__device__ __forceinline__ float rcpf(float x) {
    float r; asm("rcp.approx.ftz.f32 %0, %1;" : "=f"(r) : "f"(x)); return r;
}
__device__ __forceinline__ void mma8(float c[4],
                                     uint32_t a0, uint32_t a1, uint32_t a2, uint32_t a3,
                                     uint32_t b0, uint32_t b1) {
    asm volatile(
        "mma.sync.aligned.m16n8k8.row.col.f32.tf32.tf32.f32 "
        "{%0,%1,%2,%3}, {%4,%5,%6,%7}, {%8,%9}, {%0,%1,%2,%3};"
        : "+f"(c[0]), "+f"(c[1]), "+f"(c[2]), "+f"(c[3])
        : "r"(a0), "r"(a1), "r"(a2), "r"(a3), "r"(b0), "r"(b1));
}

__global__ void prep_kernel(const float* __restrict__ ref) {
    const int tid = threadIdx.x;  // 512 threads
    {   // Pass-1 B table: entry (s, m, q)
        const int s = tid >> 8, rem = tid & 255, m = rem >> 2, q = rem & 3;
        const float v0 = 14.426950408889634f * ref[m * DVEC + 8 * s + q];
        const float v1 = 14.426950408889634f * ref[m * DVEC + 8 * s + q + 4];
        const uint32_t h0 = tf32h(v0), h1 = tf32h(v1);
        const uint32_t l0 = tf32h(v0 - uf(h0)), l1 = tf32h(v1 - uf(h1));
        gP1[tid] = make_float4(uf(h0), uf(h1), uf(l0), uf(l1));
    }
    {   // Pass-2 B table: entry (s, j, q), rows permuted by sigma
        const int s = tid >> 6, rem = tid & 63, j = rem >> 2, q = rem & 3;
        const float v0 = ref[(8 * s + 2 * q) * DVEC + j];
        const float v1 = ref[(8 * s + 2 * q + 1) * DVEC + j];
        const uint32_t h0 = tf32h(v0), h1 = tf32h(v1);
        const uint32_t l0 = tf32h(v0 - uf(h0)), l1 = tf32h(v1 - uf(h1));
        gPB[tid] = make_float4(uf(h0), uf(h1), uf(l0), uf(l1));
    }
    if (tid < 32) {  // bias pairs: entry (t, q)
        const int t = tid >> 2, q = tid & 3;
        const int m0 = 8 * t + 2 * q, m1 = m0 + 1;
        float s0 = 0.0f, s1 = 0.0f;
        #pragma unroll
        for (int i = 0; i < DVEC; i++) {
            s0 = fmaf(ref[m0 * DVEC + i], ref[m0 * DVEC + i], s0);
            s1 = fmaf(ref[m1 * DVEC + i], ref[m1 * DVEC + i], s1);
        }
        gB2[tid] = make_float2(-7.2134752044448169f * s0,
                               -7.2134752044448169f * s1);
    }
}

__global__ __launch_bounds__(TPB)
void stq_kernel(const float* __restrict__ x, float* __restrict__ out) {
    __shared__ __align__(16) float4 sP1[512];
    __shared__ __align__(16) float4 sPB[512];
    __shared__ float2 sB2[32];

    const int tid = threadIdx.x;
    #pragma unroll
    for (int i = tid; i < 512; i += TPB) { sP1[i] = gP1[i]; sPB[i] = gPB[i]; }
    if (tid < 32) sB2[tid] = gB2[tid];
    __syncthreads();

    const int warp = tid >> 5;
    const int lane = tid & 31;
    const int g = lane >> 2;     // groupID (row within tile)
    const int q = lane & 3;      // threadID in group

    const int tp = (blockIdx.x * 4 + warp) * 2;   // tile pair base
    const int vA  = tp * 16 + g;                  // tile A rows
    const int vA8 = vA + 8;
    const int vB  = vA + 16;                      // tile B rows
    const int vB8 = vB + 8;

    // ---- Load A fragments for pass 1 (both tiles), split hi/lo ----
    uint32_t xhA[2][4], xlA[2][4], xhB[2][4], xlB[2][4];
    {
        const float* a0 = x + (size_t)vA  * DVEC;
        const float* a1 = x + (size_t)vA8 * DVEC;
        const float* b0 = x + (size_t)vB  * DVEC;
        const float* b1 = x + (size_t)vB8 * DVEC;
        #pragma unroll
        for (int s = 0; s < 2; s++) {
            float v;
            v = a0[8 * s + q];     xhA[s][0] = tf32h(v); xlA[s][0] = tf32h(v - uf(xhA[s][0]));
            v = a1[8 * s + q];     xhA[s][1] = tf32h(v); xlA[s][1] = tf32h(v - uf(xhA[s][1]));
            v = a0[8 * s + q + 4]; xhA[s][2] = tf32h(v); xlA[s][2] = tf32h(v - uf(xhA[s][2]));
            v = a1[8 * s + q + 4]; xhA[s][3] = tf32h(v); xlA[s][3] = tf32h(v - uf(xhA[s][3]));
            v = b0[8 * s + q];     xhB[s][0] = tf32h(v); xlB[s][0] = tf32h(v - uf(xhB[s][0]));
            v = b1[8 * s + q];     xhB[s][1] = tf32h(v); xlB[s][1] = tf32h(v - uf(xhB[s][1]));
            v = b0[8 * s + q + 4]; xhB[s][2] = tf32h(v); xlB[s][2] = tf32h(v - uf(xhB[s][2]));
            v = b1[8 * s + q + 4]; xhB[s][3] = tf32h(v); xlB[s][3] = tf32h(v - uf(xhB[s][3]));
        }
    }

    // ---- Pass 1: logits for both tiles; each B load feeds 6 MMAs ----
    float cA[8][4], cB[8][4];
    #pragma unroll
    for (int t = 0; t < 8; t++) {
        cA[t][0] = cA[t][1] = cA[t][2] = cA[t][3] = 0.0f;
        cB[t][0] = cB[t][1] = cB[t][2] = cB[t][3] = 0.0f;
    }

    #pragma unroll
    for (int t = 0; t < 8; t++) {
        #pragma unroll
        for (int s = 0; s < 2; s++) {
            float4 B = sP1[(s * 64 + 8 * t + g) * 4 + q];
            const uint32_t bh0 = __float_as_uint(B.x), bh1 = __float_as_uint(B.y);
            const uint32_t bl0 = __float_as_uint(B.z), bl1 = __float_as_uint(B.w);
            mma8(cA[t], xhA[s][0], xhA[s][1], xhA[s][2], xhA[s][3], bh0, bh1);
            mma8(cA[t], xhA[s][0], xhA[s][1], xhA[s][2], xhA[s][3], bl0, bl1);
            mma8(cA[t], xlA[s][0], xlA[s][1], xlA[s][2], xlA[s][3], bh0, bh1);
            mma8(cB[t], xhB[s][0], xhB[s][1], xhB[s][2], xhB[s][3], bh0, bh1);
            mma8(cB[t], xhB[s][0], xhB[s][1], xhB[s][2], xhB[s][3], bl0, bl1);
            mma8(cB[t], xlB[s][0], xlB[s][1], xlB[s][2], xlB[s][3], bh0, bh1);
        }
    }

    // ---- bias add ----
    #pragma unroll
    for (int t = 0; t < 8; t++) {
        float2 bb = sB2[t * 4 + q];
        cA[t][0] += bb.x; cA[t][1] += bb.y; cA[t][2] += bb.x; cA[t][3] += bb.y;
        cB[t][0] += bb.x; cB[t][1] += bb.y; cB[t][2] += bb.x; cB[t][3] += bb.y;
    }

    // ---- row maxes ----
    float mgA = fmaxf(cA[0][0], cA[0][1]), m8A = fmaxf(cA[0][2], cA[0][3]);
    float mgB = fmaxf(cB[0][0], cB[0][1]), m8B = fmaxf(cB[0][2], cB[0][3]);
    #pragma unroll
    for (int t = 1; t < 8; t++) {
        mgA = fmaxf(mgA, fmaxf(cA[t][0], cA[t][1]));
        m8A = fmaxf(m8A, fmaxf(cA[t][2], cA[t][3]));
        mgB = fmaxf(mgB, fmaxf(cB[t][0], cB[t][1]));
        m8B = fmaxf(m8B, fmaxf(cB[t][2], cB[t][3]));
    }
    mgA = fmaxf(mgA, __shfl_xor_sync(0xffffffffu, mgA, 1));
    mgA = fmaxf(mgA, __shfl_xor_sync(0xffffffffu, mgA, 2));
    m8A = fmaxf(m8A, __shfl_xor_sync(0xffffffffu, m8A, 1));
    m8A = fmaxf(m8A, __shfl_xor_sync(0xffffffffu, m8A, 2));
    mgB = fmaxf(mgB, __shfl_xor_sync(0xffffffffu, mgB, 1));
    mgB = fmaxf(mgB, __shfl_xor_sync(0xffffffffu, mgB, 2));
    m8B = fmaxf(m8B, __shfl_xor_sync(0xffffffffu, m8B, 1));
    m8B = fmaxf(m8B, __shfl_xor_sync(0xffffffffu, m8B, 2));

    // ---- Pass 2 fused with exp; each B load feeds 6 MMAs ----
    float zA[2][4], zB[2][4];
    #pragma unroll
    for (int nt = 0; nt < 2; nt++) {
        zA[nt][0] = zA[nt][1] = zA[nt][2] = zA[nt][3] = 0.0f;
        zB[nt][0] = zB[nt][1] = zB[nt][2] = zB[nt][3] = 0.0f;
    }
    float sgA = 0.0f, s8A = 0.0f, sgB = 0.0f, s8B = 0.0f;

    #pragma unroll
    for (int s = 0; s < 8; s++) {
        const float eA0 = ex2f(cA[s][0] - mgA);
        const float eA1 = ex2f(cA[s][1] - mgA);
        const float eA2 = ex2f(cA[s][2] - m8A);
        const float eA3 = ex2f(cA[s][3] - m8A);
        sgA += eA0 + eA1;  s8A += eA2 + eA3;
        const float eB0 = ex2f(cB[s][0] - mgB);
        const float eB1 = ex2f(cB[s][1] - mgB);
        const float eB2 = ex2f(cB[s][2] - m8B);
        const float eB3 = ex2f(cB[s][3] - m8B);
        sgB += eB0 + eB1;  s8B += eB2 + eB3;

        const uint32_t ahA0 = tf32h(eA0), ahA1 = tf32h(eA2), ahA2 = tf32h(eA1), ahA3 = tf32h(eA3);
        const uint32_t alA0 = tf32h(eA0 - uf(ahA0)), alA1 = tf32h(eA2 - uf(ahA1));
        const uint32_t alA2 = tf32h(eA1 - uf(ahA2)), alA3 = tf32h(eA3 - uf(ahA3));
        const uint32_t ahB0 = tf32h(eB0), ahB1 = tf32h(eB2), ahB2 = tf32h(eB1), ahB3 = tf32h(eB3);
        const uint32_t alB0 = tf32h(eB0 - uf(ahB0)), alB1 = tf32h(eB2 - uf(ahB1));
        const uint32_t alB2 = tf32h(eB1 - uf(ahB2)), alB3 = tf32h(eB3 - uf(ahB3));

        #pragma unroll
        for (int nt = 0; nt < 2; nt++) {
            float4 B = sPB[(s * 16 + 8 * nt + g) * 4 + q];
            const uint32_t bh0 = __float_as_uint(B.x), bh1 = __float_as_uint(B.y);
            const uint32_t bl0 = __float_as_uint(B.z), bl1 = __float_as_uint(B.w);
            mma8(zA[nt], ahA0, ahA1, ahA2, ahA3, bh0, bh1);
            mma8(zA[nt], ahA0, ahA1, ahA2, ahA3, bl0, bl1);
            mma8(zA[nt], alA0, alA1, alA2, alA3, bh0, bh1);
            mma8(zB[nt], ahB0, ahB1, ahB2, ahB3, bh0, bh1);
            mma8(zB[nt], ahB0, ahB1, ahB2, ahB3, bl0, bl1);
            mma8(zB[nt], alB0, alB1, alB2, alB3, bh0, bh1);
        }
    }

    // ---- normalize + store ----
    sgA += __shfl_xor_sync(0xffffffffu, sgA, 1);
    sgA += __shfl_xor_sync(0xffffffffu, sgA, 2);
    s8A += __shfl_xor_sync(0xffffffffu, s8A, 1);
    s8A += __shfl_xor_sync(0xffffffffu, s8A, 2);
    sgB += __shfl_xor_sync(0xffffffffu, sgB, 1);
    sgB += __shfl_xor_sync(0xffffffffu, sgB, 2);
    s8B += __shfl_xor_sync(0xffffffffu, s8B, 1);
    s8B += __shfl_xor_sync(0xffffffffu, s8B, 2);
    const float igA = rcpf(sgA), i8A = rcpf(s8A);
    const float igB = rcpf(sgB), i8B = rcpf(s8B);

    #pragma unroll
    for (int nt = 0; nt < 2; nt++) {
        *reinterpret_cast<float2*>(out + (size_t)vA  * DVEC + 8 * nt + 2 * q) =
            make_float2(zA[nt][0] * igA, zA[nt][1] * igA);
        *reinterpret_cast<float2*>(out + (size_t)vA8 * DVEC + 8 * nt + 2 * q) =
            make_float2(zA[nt][2] * i8A, zA[nt][3] * i8A);
        *reinterpret_cast<float2*>(out + (size_t)vB  * DVEC + 8 * nt + 2 * q) =
            make_float2(zB[nt][0] * igB, zB[nt][1] * igB);
        *reinterpret_cast<float2*>(out + (size_t)vB8 * DVEC + 8 * nt + 2 * q) =
            make_float2(zB[nt][2] * i8B, zB[nt][3] * i8B);
    }
}

extern "C" void kernel_launch(void* const* d_in, const int* in_sizes, int n_in,
                              void* d_out, int out_size) {
    const float* x   = (const float*)d_in[0];   // (64,8,32,32,16) f32
    const float* ref = (const float*)d_in[1];   // (64,16) f32
    float* out = (float*)d_out;

    prep_kernel<<<1, 512>>>(ref);

    const int nvec = in_sizes[0] / DVEC;        // 524288
    const int tiles = nvec / 16;                // 32768
    const int blocks = tiles / 8;               // 4096 (4 warps x 2 tiles)
    stq_kernel<<<blocks, TPB>>>(x, out);
}

// round 10
// speedup vs baseline: 1.5161x; 1.5161x over previous
#include <cuda_runtime.h>
#include <cstdint>

// soft_to_hard_quantize via bf16 tensor cores (mma.m16n8k16, 3-term split).
// R10: tf32 k8 -> bf16 k16 halves MMA instruction count (the legacy mma.sync
// path appears throughput-capped at ~52% of ncu's tensor peak in R8/R9).
// Error compensation: v = bf16(v) + bf16(v - bf16(v)); compute hh + h*lo_b +
// lo_a*h (dropped lo*lo ~ 2^-18 rel). Pass-1 C fragments map directly onto
// pass-2 A fragments with k16 (no codeword permutation needed).
//
// logit[v][m] = 14.4269504*dot(x_v, r_m) - 7.2134752*||r_m||^2   (log2 domain)
// e = exp2(logit - rowmax);  z_v = sum_m e*r_m / sum_m e

#define TPB   128   // 4 warps/block, 2 tiles (32 vectors) per warp
#define DVEC  16

// Packed bf16 codebook tables (built by prep kernel). uint4 = {hi01, hi89, lo01, lo89}
__device__ uint4  gP1[256];   // pass-1 B: idx = m*4+q,  pairs (k=2q,2q+1) & (k=2q+8,2q+9) of 14.43*r[m][k]
__device__ uint4  gPB[256];   // pass-2 B: idx = ((s*2+nt)*8+g)*4+q, pairs r[16s+2q(+1)][8nt+g] & r[16s+2q+8(+9)][8nt+g]
__device__ float2 gB2[32];    // bias: idx = t*4+q -> {b2[8t+2q], b2[8t+2q+1]}

__device__ __forceinline__ uint32_t pkbf(float lo_elem, float hi_elem) {
    // bf16x2: lower 16 bits = lo_elem (even k), upper = hi_elem (odd k)
    uint32_t r;
    asm("cvt.rn.bf16x2.f32 %0, %1, %2;" : "=r"(r) : "f"(hi_elem), "f"(lo_elem));
    return r;
}
__device__ __forceinline__ float bflo(uint32_t u) { return __uint_as_float(u << 16); }
__device__ __forceinline__ float bfhi(uint32_t u) { return __uint_as_float(u & 0xffff0000u); }
__device__ __forceinline__ float ex2f(float x) {
    float r; asm("ex2.approx.ftz.f32 %0, %1;" : "=f"(r) : "f"(x)); return r;
}
__device__ __forceinline__ float rcpf(float x) {
    float r; asm("rcp.approx.ftz.f32 %0, %1;" : "=f"(r) : "f"(x)); return r;
}
__device__ __forceinline__ void mma16(float c[4],
                                      uint32_t a0, uint32_t a1, uint32_t a2, uint32_t a3,
                                      uint32_t b0, uint32_t b1) {
    asm volatile(
        "mma.sync.aligned.m16n8k16.row.col.f32.bf16.bf16.f32 "
        "{%0,%1,%2,%3}, {%4,%5,%6,%7}, {%8,%9}, {%0,%1,%2,%3};"
        : "+f"(c[0]), "+f"(c[1]), "+f"(c[2]), "+f"(c[3])
        : "r"(a0), "r"(a1), "r"(a2), "r"(a3), "r"(b0), "r"(b1));
}
__device__ __forceinline__ uint4 split4(float v0, float v1, float v2, float v3) {
    uint4 r;
    r.x = pkbf(v0, v1);
    r.y = pkbf(v2, v3);
    r.z = pkbf(v0 - bflo(r.x), v1 - bfhi(r.x));
    r.w = pkbf(v2 - bflo(r.y), v3 - bfhi(r.y));
    return r;
}

__global__ void prep_kernel(const float* __restrict__ ref) {
    const int tid = threadIdx.x;  // 256 threads
    {   // Pass-1 B table: (m, q)
        const int m = tid >> 2, q = tid & 3;
        const float S = 14.426950408889634f;   // 10*log2(e)
        const float* b = ref + m * DVEC;
        gP1[tid] = split4(S * b[2 * q], S * b[2 * q + 1],
                          S * b[2 * q + 8], S * b[2 * q + 9]);
    }
    {   // Pass-2 B table: (s, nt, g, q)
        const int q = tid & 3, g = (tid >> 2) & 7, nt = (tid >> 5) & 1, s = tid >> 6;
        const int j = 8 * nt + g;
        gPB[tid] = split4(ref[(16 * s + 2 * q) * DVEC + j],
                          ref[(16 * s + 2 * q + 1) * DVEC + j],
                          ref[(16 * s + 2 * q + 8) * DVEC + j],
                          ref[(16 * s + 2 * q + 9) * DVEC + j]);
    }
    if (tid < 32) {  // bias pairs: (t, q)
        const int t = tid >> 2, q = tid & 3;
        const int m0 = 8 * t + 2 * q, m1 = m0 + 1;
        float s0 = 0.0f, s1 = 0.0f;
        #pragma unroll
        for (int i = 0; i < DVEC; i++) {
            s0 = fmaf(ref[m0 * DVEC + i], ref[m0 * DVEC + i], s0);
            s1 = fmaf(ref[m1 * DVEC + i], ref[m1 * DVEC + i], s1);
        }
        gB2[tid] = make_float2(-7.2134752044448169f * s0,
                               -7.2134752044448169f * s1);
    }
}

__global__ __launch_bounds__(TPB)
void stq_kernel(const float* __restrict__ x, float* __restrict__ out) {
    __shared__ __align__(16) uint4 sP1[256];
    __shared__ __align__(16) uint4 sPB[256];
    __shared__ float2 sB2[32];

    const int tid = threadIdx.x;
    #pragma unroll
    for (int i = tid; i < 256; i += TPB) { sP1[i] = gP1[i]; sPB[i] = gPB[i]; }
    if (tid < 32) sB2[tid] = gB2[tid];
    __syncthreads();

    const int warp = tid >> 5;
    const int lane = tid & 31;
    const int g = lane >> 2;     // groupID
    const int q = lane & 3;      // threadID in group

    const int tp = (blockIdx.x * 4 + warp) * 2;   // tile pair base
    const int vA  = tp * 16 + g;
    const int vA8 = vA + 8;
    const int vB  = vA + 16;
    const int vB8 = vB + 8;

    // ---- Load + split pass-1 A fragments (both tiles) ----
    // a0={X[g][2q],X[g][2q+1]}, a1={X[g+8][..]}, a2={X[g][2q+8],2q+9}, a3={X[g+8][..]}
    uint32_t ahA[4], alA[4], ahB[4], alB[4];
    {
        const float2 pA00 = *reinterpret_cast<const float2*>(x + (size_t)vA  * DVEC + 2 * q);
        const float2 pA08 = *reinterpret_cast<const float2*>(x + (size_t)vA  * DVEC + 2 * q + 8);
        const float2 pA10 = *reinterpret_cast<const float2*>(x + (size_t)vA8 * DVEC + 2 * q);
        const float2 pA18 = *reinterpret_cast<const float2*>(x + (size_t)vA8 * DVEC + 2 * q + 8);
        ahA[0] = pkbf(pA00.x, pA00.y); alA[0] = pkbf(pA00.x - bflo(ahA[0]), pA00.y - bfhi(ahA[0]));
        ahA[1] = pkbf(pA10.x, pA10.y); alA[1] = pkbf(pA10.x - bflo(ahA[1]), pA10.y - bfhi(ahA[1]));
        ahA[2] = pkbf(pA08.x, pA08.y); alA[2] = pkbf(pA08.x - bflo(ahA[2]), pA08.y - bfhi(ahA[2]));
        ahA[3] = pkbf(pA18.x, pA18.y); alA[3] = pkbf(pA18.x - bflo(ahA[3]), pA18.y - bfhi(ahA[3]));
        const float2 pB00 = *reinterpret_cast<const float2*>(x + (size_t)vB  * DVEC + 2 * q);
        const float2 pB08 = *reinterpret_cast<const float2*>(x + (size_t)vB  * DVEC + 2 * q + 8);
        const float2 pB10 = *reinterpret_cast<const float2*>(x + (size_t)vB8 * DVEC + 2 * q);
        const float2 pB18 = *reinterpret_cast<const float2*>(x + (size_t)vB8 * DVEC + 2 * q + 8);
        ahB[0] = pkbf(pB00.x, pB00.y); alB[0] = pkbf(pB00.x - bflo(ahB[0]), pB00.y - bfhi(ahB[0]));
        ahB[1] = pkbf(pB10.x, pB10.y); alB[1] = pkbf(pB10.x - bflo(ahB[1]), pB10.y - bfhi(ahB[1]));
        ahB[2] = pkbf(pB08.x, pB08.y); alB[2] = pkbf(pB08.x - bflo(ahB[2]), pB08.y - bfhi(ahB[2]));
        ahB[3] = pkbf(pB18.x, pB18.y); alB[3] = pkbf(pB18.x - bflo(ahB[3]), pB18.y - bfhi(ahB[3]));
    }

    // ---- Pass 1: logits; one k16 step per n-tile; each B load feeds 6 MMAs ----
    float cA[8][4], cB[8][4];
    #pragma unroll
    for (int t = 0; t < 8; t++) {
        cA[t][0] = cA[t][1] = cA[t][2] = cA[t][3] = 0.0f;
        cB[t][0] = cB[t][1] = cB[t][2] = cB[t][3] = 0.0f;
    }
    #pragma unroll
    for (int t = 0; t < 8; t++) {
        uint4 P = sP1[(8 * t + g) * 4 + q];
        mma16(cA[t], ahA[0], ahA[1], ahA[2], ahA[3], P.x, P.y);
        mma16(cA[t], ahA[0], ahA[1], ahA[2], ahA[3], P.z, P.w);
        mma16(cA[t], alA[0], alA[1], alA[2], alA[3], P.x, P.y);
        mma16(cB[t], ahB[0], ahB[1], ahB[2], ahB[3], P.x, P.y);
        mma16(cB[t], ahB[0], ahB[1], ahB[2], ahB[3], P.z, P.w);
        mma16(cB[t], alB[0], alB[1], alB[2], alB[3], P.x, P.y);
    }

    // ---- bias add: c[t][0..1] -> m=8t+2q(+1) rows g / c[t][2..3] rows g+8 ----
    #pragma unroll
    for (int t = 0; t < 8; t++) {
        float2 bb = sB2[t * 4 + q];
        cA[t][0] += bb.x; cA[t][1] += bb.y; cA[t][2] += bb.x; cA[t][3] += bb.y;
        cB[t][0] += bb.x; cB[t][1] += bb.y; cB[t][2] += bb.x; cB[t][3] += bb.y;
    }

    // ---- row maxes ----
    float mgA = fmaxf(cA[0][0], cA[0][1]), m8A = fmaxf(cA[0][2], cA[0][3]);
    float mgB = fmaxf(cB[0][0], cB[0][1]), m8B = fmaxf(cB[0][2], cB[0][3]);
    #pragma unroll
    for (int t = 1; t < 8; t++) {
        mgA = fmaxf(mgA, fmaxf(cA[t][0], cA[t][1]));
        m8A = fmaxf(m8A, fmaxf(cA[t][2], cA[t][3]));
        mgB = fmaxf(mgB, fmaxf(cB[t][0], cB[t][1]));
        m8B = fmaxf(m8B, fmaxf(cB[t][2], cB[t][3]));
    }
    mgA = fmaxf(mgA, __shfl_xor_sync(0xffffffffu, mgA, 1));
    mgA = fmaxf(mgA, __shfl_xor_sync(0xffffffffu, mgA, 2));
    m8A = fmaxf(m8A, __shfl_xor_sync(0xffffffffu, m8A, 1));
    m8A = fmaxf(m8A, __shfl_xor_sync(0xffffffffu, m8A, 2));
    mgB = fmaxf(mgB, __shfl_xor_sync(0xffffffffu, mgB, 1));
    mgB = fmaxf(mgB, __shfl_xor_sync(0xffffffffu, mgB, 2));
    m8B = fmaxf(m8B, __shfl_xor_sync(0xffffffffu, m8B, 1));
    m8B = fmaxf(m8B, __shfl_xor_sync(0xffffffffu, m8B, 2));

    // ---- Pass 2 fused with exp; c[2s]/c[2s+1] ARE the k16 A fragment ----
    float zA[2][4], zB[2][4];
    #pragma unroll
    for (int nt = 0; nt < 2; nt++) {
        zA[nt][0] = zA[nt][1] = zA[nt][2] = zA[nt][3] = 0.0f;
        zB[nt][0] = zB[nt][1] = zB[nt][2] = zB[nt][3] = 0.0f;
    }
    float sgA = 0.0f, s8A = 0.0f, sgB = 0.0f, s8B = 0.0f;

    #pragma unroll
    for (int s = 0; s < 4; s++) {
        // tile A exps: a0={e(g,16s+2q),e(g,16s+2q+1)}, a1=rows g+8, a2/a3 from c[2s+1]
        const float eA00 = ex2f(cA[2*s][0]   - mgA), eA01 = ex2f(cA[2*s][1]   - mgA);
        const float eA02 = ex2f(cA[2*s][2]   - m8A), eA03 = ex2f(cA[2*s][3]   - m8A);
        const float eA10 = ex2f(cA[2*s+1][0] - mgA), eA11 = ex2f(cA[2*s+1][1] - mgA);
        const float eA12 = ex2f(cA[2*s+1][2] - m8A), eA13 = ex2f(cA[2*s+1][3] - m8A);
        sgA += (eA00 + eA01) + (eA10 + eA11);
        s8A += (eA02 + eA03) + (eA12 + eA13);
        uint32_t a0h = pkbf(eA00, eA01), a1h = pkbf(eA02, eA03);
        uint32_t a2h = pkbf(eA10, eA11), a3h = pkbf(eA12, eA13);
        uint32_t a0l = pkbf(eA00 - bflo(a0h), eA01 - bfhi(a0h));
        uint32_t a1l = pkbf(eA02 - bflo(a1h), eA03 - bfhi(a1h));
        uint32_t a2l = pkbf(eA10 - bflo(a2h), eA11 - bfhi(a2h));
        uint32_t a3l = pkbf(eA12 - bflo(a3h), eA13 - bfhi(a3h));

        const float eB00 = ex2f(cB[2*s][0]   - mgB), eB01 = ex2f(cB[2*s][1]   - mgB);
        const float eB02 = ex2f(cB[2*s][2]   - m8B), eB03 = ex2f(cB[2*s][3]   - m8B);
        const float eB10 = ex2f(cB[2*s+1][0] - mgB), eB11 = ex2f(cB[2*s+1][1] - mgB);
        const float eB12 = ex2f(cB[2*s+1][2] - m8B), eB13 = ex2f(cB[2*s+1][3] - m8B);
        sgB += (eB00 + eB01) + (eB10 + eB11);
        s8B += (eB02 + eB03) + (eB12 + eB13);
        uint32_t b0h = pkbf(eB00, eB01), b1h = pkbf(eB02, eB03);
        uint32_t b2h = pkbf(eB10, eB11), b3h = pkbf(eB12, eB13);
        uint32_t b0l = pkbf(eB00 - bflo(b0h), eB01 - bfhi(b0h));
        uint32_t b1l = pkbf(eB02 - bflo(b1h), eB03 - bfhi(b1h));
        uint32_t b2l = pkbf(eB10 - bflo(b2h), eB11 - bfhi(b2h));
        uint32_t b3l = pkbf(eB12 - bflo(b3h), eB13 - bfhi(b3h));

        #pragma unroll
        for (int nt = 0; nt < 2; nt++) {
            uint4 P = sPB[((s * 2 + nt) * 8 + g) * 4 + q];
            mma16(zA[nt], a0h, a1h, a2h, a3h, P.x, P.y);
            mma16(zA[nt], a0h, a1h, a2h, a3h, P.z, P.w);
            mma16(zA[nt], a0l, a1l, a2l, a3l, P.x, P.y);
            mma16(zB[nt], b0h, b1h, b2h, b3h, P.x, P.y);
            mma16(zB[nt], b0h, b1h, b2h, b3h, P.z, P.w);
            mma16(zB[nt], b0l, b1l, b2l, b3l, P.x, P.y);
        }
    }

    // ---- normalize + store ----
    sgA += __shfl_xor_sync(0xffffffffu, sgA, 1);
    sgA += __shfl_xor_sync(0xffffffffu, sgA, 2);
    s8A += __shfl_xor_sync(0xffffffffu, s8A, 1);
    s8A += __shfl_xor_sync(0xffffffffu, s8A, 2);
    sgB += __shfl_xor_sync(0xffffffffu, sgB, 1);
    sgB += __shfl_xor_sync(0xffffffffu, sgB, 2);
    s8B += __shfl_xor_sync(0xffffffffu, s8B, 1);
    s8B += __shfl_xor_sync(0xffffffffu, s8B, 2);
    const float igA = rcpf(sgA), i8A = rcpf(s8A);
    const float igB = rcpf(sgB), i8B = rcpf(s8B);

    #pragma unroll
    for (int nt = 0; nt < 2; nt++) {
        *reinterpret_cast<float2*>(out + (size_t)vA  * DVEC + 8 * nt + 2 * q) =
            make_float2(zA[nt][0] * igA, zA[nt][1] * igA);
        *reinterpret_cast<float2*>(out + (size_t)vA8 * DVEC + 8 * nt + 2 * q) =
            make_float2(zA[nt][2] * i8A, zA[nt][3] * i8A);
        *reinterpret_cast<float2*>(out + (size_t)vB  * DVEC + 8 * nt + 2 * q) =
            make_float2(zB[nt][0] * igB, zB[nt][1] * igB);
        *reinterpret_cast<float2*>(out + (size_t)vB8 * DVEC + 8 * nt + 2 * q) =
            make_float2(zB[nt][2] * i8B, zB[nt][3] * i8B);
    }
}

extern "C" void kernel_launch(void* const* d_in, const int* in_sizes, int n_in,
                              void* d_out, int out_size) {
    const float* x   = (const float*)d_in[0];   // (64,8,32,32,16) f32
    const float* ref = (const float*)d_in[1];   // (64,16) f32
    float* out = (float*)d_out;

    prep_kernel<<<1, 256>>>(ref);

    const int nvec = in_sizes[0] / DVEC;        // 524288
    const int tiles = nvec / 16;                // 32768
    const int blocks = tiles / 8;               // 4096 (4 warps x 2 tiles)
    stq_kernel<<<blocks, TPB>>>(x, out);
}

// round 12
// speedup vs baseline: 1.8008x; 1.1877x over previous
#include <cuda_runtime.h>
#include <cstdint>

// soft_to_hard_quantize via fp16 tensor cores (mma.m16n8k16).
// R11 vs R10: bf16 -> fp16. Pass 1 stays 3-term (error now ~2^-24, negligible).
// Pass 2 drops to 2 terms with CONSISTENT weights: E rounded once to fp16 and
// the softmax denominator sums exactly those rounded values, so z is the exact
// softmax of 2^-12-perturbed weights (est err ~2e-5). Bias folded into the
// pass-1 accumulator init. Net: -150 scalar issues and -16 HMMA per warp.
//
// logit[v][m] = 14.4269504*dot(x_v, r_m) - 7.2134752*||r_m||^2   (log2 domain)
// e = exp2(logit - rowmax);  z_v = sum_m e*r_m / sum_m e

#define TPB   128   // 4 warps/block, 2 tiles (32 vectors) per warp
#define DVEC  16

// Packed fp16 codebook tables. uint4 = {hi01, hi89, lo01, lo89}
__device__ uint4  gP1[256];   // pass-1 B: idx = m*4+q, pairs (k=2q,2q+1)&(k=2q+8,2q+9) of 14.43*r[m][k]
__device__ uint4  gPB[256];   // pass-2 B: idx = ((s*2+nt)*8+g)*4+q
__device__ float2 gB2[32];    // bias: idx = t*4+q -> {b2[8t+2q], b2[8t+2q+1]}

__device__ __forceinline__ uint32_t pkhf(float lo_elem, float hi_elem) {
    uint32_t r;
    asm("cvt.rn.f16x2.f32 %0, %1, %2;" : "=r"(r) : "f"(hi_elem), "f"(lo_elem));
    return r;
}
__device__ __forceinline__ float hf0(uint32_t u) {
    float f;
    asm("{ .reg .b16 l, h; mov.b32 {l, h}, %1; cvt.f32.f16 %0, l; }" : "=f"(f) : "r"(u));
    return f;
}
__device__ __forceinline__ float hf1(uint32_t u) {
    float f;
    asm("{ .reg .b16 l, h; mov.b32 {l, h}, %1; cvt.f32.f16 %0, h; }" : "=f"(f) : "r"(u));
    return f;
}
__device__ __forceinline__ float ex2f(float x) {
    float r; asm("ex2.approx.ftz.f32 %0, %1;" : "=f"(r) : "f"(x)); return r;
}
__device__ __forceinline__ float rcpf(float x) {
    float r; asm("rcp.approx.ftz.f32 %0, %1;" : "=f"(r) : "f"(x)); return r;
}
__device__ __forceinline__ void mma16(float c[4],
                                      uint32_t a0, uint32_t a1, uint32_t a2, uint32_t a3,
                                      uint32_t b0, uint32_t b1) {
    asm volatile(
        "mma.sync.aligned.m16n8k16.row.col.f32.f16.f16.f32 "
        "{%0,%1,%2,%3}, {%4,%5,%6,%7}, {%8,%9}, {%0,%1,%2,%3};"
        : "+f"(c[0]), "+f"(c[1]), "+f"(c[2]), "+f"(c[3])
        : "r"(a0), "r"(a1), "r"(a2), "r"(a3), "r"(b0), "r"(b1));
}
__device__ __forceinline__ uint4 split4(float v0, float v1, float v2, float v3) {
    uint4 r;
    r.x = pkhf(v0, v1);
    r.y = pkhf(v2, v3);
    r.z = pkhf(v0 - hf0(r.x), v1 - hf1(r.x));
    r.w = pkhf(v2 - hf0(r.y), v3 - hf1(r.y));
    return r;
}

__global__ void prep_kernel(const float* __restrict__ ref) {
    const int tid = threadIdx.x;  // 256 threads
    {   // Pass-1 B table: (m, q)
        const int m = tid >> 2, q = tid & 3;
        const float S = 14.426950408889634f;   // 10*log2(e)
        const float* b = ref + m * DVEC;
        gP1[tid] = split4(S * b[2 * q], S * b[2 * q + 1],
                          S * b[2 * q + 8], S * b[2 * q + 9]);
    }
    {   // Pass-2 B table: (s, nt, g, q)
        const int q = tid & 3, g = (tid >> 2) & 7, nt = (tid >> 5) & 1, s = tid >> 6;
        const int j = 8 * nt + g;
        gPB[tid] = split4(ref[(16 * s + 2 * q) * DVEC + j],
                          ref[(16 * s + 2 * q + 1) * DVEC + j],
                          ref[(16 * s + 2 * q + 8) * DVEC + j],
                          ref[(16 * s + 2 * q + 9) * DVEC + j]);
    }
    if (tid < 32) {  // bias pairs: (t, q)
        const int t = tid >> 2, q = tid & 3;
        const int m0 = 8 * t + 2 * q, m1 = m0 + 1;
        float s0 = 0.0f, s1 = 0.0f;
        #pragma unroll
        for (int i = 0; i < DVEC; i++) {
            s0 = fmaf(ref[m0 * DVEC + i], ref[m0 * DVEC + i], s0);
            s1 = fmaf(ref[m1 * DVEC + i], ref[m1 * DVEC + i], s1);
        }
        gB2[tid] = make_float2(-7.2134752044448169f * s0,
                               -7.2134752044448169f * s1);
    }
}

__global__ __launch_bounds__(TPB)
void stq_kernel(const float* __restrict__ x, float* __restrict__ out) {
    __shared__ __align__(16) uint4 sP1[256];
    __shared__ __align__(16) uint4 sPB[256];
    __shared__ float2 sB2[32];

    const int tid = threadIdx.x;
    #pragma unroll
    for (int i = tid; i < 256; i += TPB) { sP1[i] = gP1[i]; sPB[i] = gPB[i]; }
    if (tid < 32) sB2[tid] = gB2[tid];
    __syncthreads();

    const int warp = tid >> 5;
    const int lane = tid & 31;
    const int g = lane >> 2;     // groupID
    const int q = lane & 3;      // threadID in group

    const int tp = (blockIdx.x * 4 + warp) * 2;   // tile pair base
    const int vA  = tp * 16 + g;
    const int vA8 = vA + 8;
    const int vB  = vA + 16;
    const int vB8 = vB + 8;

    // ---- Load + split pass-1 A fragments (both tiles), fp16 hi/lo ----
    uint32_t ahA[4], alA[4], ahB[4], alB[4];
    {
        const float2 pA00 = *reinterpret_cast<const float2*>(x + (size_t)vA  * DVEC + 2 * q);
        const float2 pA08 = *reinterpret_cast<const float2*>(x + (size_t)vA  * DVEC + 2 * q + 8);
        const float2 pA10 = *reinterpret_cast<const float2*>(x + (size_t)vA8 * DVEC + 2 * q);
        const float2 pA18 = *reinterpret_cast<const float2*>(x + (size_t)vA8 * DVEC + 2 * q + 8);
        ahA[0] = pkhf(pA00.x, pA00.y); alA[0] = pkhf(pA00.x - hf0(ahA[0]), pA00.y - hf1(ahA[0]));
        ahA[1] = pkhf(pA10.x, pA10.y); alA[1] = pkhf(pA10.x - hf0(ahA[1]), pA10.y - hf1(ahA[1]));
        ahA[2] = pkhf(pA08.x, pA08.y); alA[2] = pkhf(pA08.x - hf0(ahA[2]), pA08.y - hf1(ahA[2]));
        ahA[3] = pkhf(pA18.x, pA18.y); alA[3] = pkhf(pA18.x - hf0(ahA[3]), pA18.y - hf1(ahA[3]));
        const float2 pB00 = *reinterpret_cast<const float2*>(x + (size_t)vB  * DVEC + 2 * q);
        const float2 pB08 = *reinterpret_cast<const float2*>(x + (size_t)vB  * DVEC + 2 * q + 8);
        const float2 pB10 = *reinterpret_cast<const float2*>(x + (size_t)vB8 * DVEC + 2 * q);
        const float2 pB18 = *reinterpret_cast<const float2*>(x + (size_t)vB8 * DVEC + 2 * q + 8);
        ahB[0] = pkhf(pB00.x, pB00.y); alB[0] = pkhf(pB00.x - hf0(ahB[0]), pB00.y - hf1(ahB[0]));
        ahB[1] = pkhf(pB10.x, pB10.y); alB[1] = pkhf(pB10.x - hf0(ahB[1]), pB10.y - hf1(ahB[1]));
        ahB[2] = pkhf(pB08.x, pB08.y); alB[2] = pkhf(pB08.x - hf0(ahB[2]), pB08.y - hf1(ahB[2]));
        ahB[3] = pkhf(pB18.x, pB18.y); alB[3] = pkhf(pB18.x - hf0(ahB[3]), pB18.y - hf1(ahB[3]));
    }

    // ---- Pass 1: logits; bias pre-loaded into accumulators (no FADD later) ----
    float cA[8][4], cB[8][4];
    #pragma unroll
    for (int t = 0; t < 8; t++) {
        float2 bb = sB2[t * 4 + q];
        cA[t][0] = bb.x; cA[t][1] = bb.y; cA[t][2] = bb.x; cA[t][3] = bb.y;
        cB[t][0] = bb.x; cB[t][1] = bb.y; cB[t][2] = bb.x; cB[t][3] = bb.y;
    }
    #pragma unroll
    for (int t = 0; t < 8; t++) {
        uint4 P = sP1[(8 * t + g) * 4 + q];
        mma16(cA[t], ahA[0], ahA[1], ahA[2], ahA[3], P.x, P.y);
        mma16(cA[t], ahA[0], ahA[1], ahA[2], ahA[3], P.z, P.w);
        mma16(cA[t], alA[0], alA[1], alA[2], alA[3], P.x, P.y);
        mma16(cB[t], ahB[0], ahB[1], ahB[2], ahB[3], P.x, P.y);
        mma16(cB[t], ahB[0], ahB[1], ahB[2], ahB[3], P.z, P.w);
        mma16(cB[t], alB[0], alB[1], alB[2], alB[3], P.x, P.y);
    }

    // ---- row maxes ----
    float mgA = fmaxf(cA[0][0], cA[0][1]), m8A = fmaxf(cA[0][2], cA[0][3]);
    float mgB = fmaxf(cB[0][0], cB[0][1]), m8B = fmaxf(cB[0][2], cB[0][3]);
    #pragma unroll
    for (int t = 1; t < 8; t++) {
        mgA = fmaxf(mgA, fmaxf(cA[t][0], cA[t][1]));
        m8A = fmaxf(m8A, fmaxf(cA[t][2], cA[t][3]));
        mgB = fmaxf(mgB, fmaxf(cB[t][0], cB[t][1]));
        m8B = fmaxf(m8B, fmaxf(cB[t][2], cB[t][3]));
    }
    mgA = fmaxf(mgA, __shfl_xor_sync(0xffffffffu, mgA, 1));
    mgA = fmaxf(mgA, __shfl_xor_sync(0xffffffffu, mgA, 2));
    m8A = fmaxf(m8A, __shfl_xor_sync(0xffffffffu, m8A, 1));
    m8A = fmaxf(m8A, __shfl_xor_sync(0xffffffffu, m8A, 2));
    mgB = fmaxf(mgB, __shfl_xor_sync(0xffffffffu, mgB, 1));
    mgB = fmaxf(mgB, __shfl_xor_sync(0xffffffffu, mgB, 2));
    m8B = fmaxf(m8B, __shfl_xor_sync(0xffffffffu, m8B, 1));
    m8B = fmaxf(m8B, __shfl_xor_sync(0xffffffffu, m8B, 2));

    // ---- Pass 2: exp -> fp16 ONCE (consistent weights), 2-term MMA ----
    float zA[2][4], zB[2][4];
    #pragma unroll
    for (int nt = 0; nt < 2; nt++) {
        zA[nt][0] = zA[nt][1] = zA[nt][2] = zA[nt][3] = 0.0f;
        zB[nt][0] = zB[nt][1] = zB[nt][2] = zB[nt][3] = 0.0f;
    }
    float sgA = 0.0f, s8A = 0.0f, sgB = 0.0f, s8B = 0.0f;

    #pragma unroll
    for (int s = 0; s < 4; s++) {
        // tile A: pack exps to fp16 fragments, then sum the ROUNDED values
        uint32_t a0h = pkhf(ex2f(cA[2*s][0]   - mgA), ex2f(cA[2*s][1]   - mgA));
        uint32_t a1h = pkhf(ex2f(cA[2*s][2]   - m8A), ex2f(cA[2*s][3]   - m8A));
        uint32_t a2h = pkhf(ex2f(cA[2*s+1][0] - mgA), ex2f(cA[2*s+1][1] - mgA));
        uint32_t a3h = pkhf(ex2f(cA[2*s+1][2] - m8A), ex2f(cA[2*s+1][3] - m8A));
        sgA += (hf0(a0h) + hf1(a0h)) + (hf0(a2h) + hf1(a2h));
        s8A += (hf0(a1h) + hf1(a1h)) + (hf0(a3h) + hf1(a3h));

        uint32_t b0h = pkhf(ex2f(cB[2*s][0]   - mgB), ex2f(cB[2*s][1]   - mgB));
        uint32_t b1h = pkhf(ex2f(cB[2*s][2]   - m8B), ex2f(cB[2*s][3]   - m8B));
        uint32_t b2h = pkhf(ex2f(cB[2*s+1][0] - mgB), ex2f(cB[2*s+1][1] - mgB));
        uint32_t b3h = pkhf(ex2f(cB[2*s+1][2] - m8B), ex2f(cB[2*s+1][3] - m8B));
        sgB += (hf0(b0h) + hf1(b0h)) + (hf0(b2h) + hf1(b2h));
        s8B += (hf0(b1h) + hf1(b1h)) + (hf0(b3h) + hf1(b3h));

        #pragma unroll
        for (int nt = 0; nt < 2; nt++) {
            uint4 P = sPB[((s * 2 + nt) * 8 + g) * 4 + q];
            mma16(zA[nt], a0h, a1h, a2h, a3h, P.x, P.y);
            mma16(zA[nt], a0h, a1h, a2h, a3h, P.z, P.w);
            mma16(zB[nt], b0h, b1h, b2h, b3h, P.x, P.y);
            mma16(zB[nt], b0h, b1h, b2h, b3h, P.z, P.w);
        }
    }

    // ---- normalize + store ----
    sgA += __shfl_xor_sync(0xffffffffu, sgA, 1);
    sgA += __shfl_xor_sync(0xffffffffu, sgA, 2);
    s8A += __shfl_xor_sync(0xffffffffu, s8A, 1);
    s8A += __shfl_xor_sync(0xffffffffu, s8A, 2);
    sgB += __shfl_xor_sync(0xffffffffu, sgB, 1);
    sgB += __shfl_xor_sync(0xffffffffu, sgB, 2);
    s8B += __shfl_xor_sync(0xffffffffu, s8B, 1);
    s8B += __shfl_xor_sync(0xffffffffu, s8B, 2);
    const float igA = rcpf(sgA), i8A = rcpf(s8A);
    const float igB = rcpf(sgB), i8B = rcpf(s8B);

    #pragma unroll
    for (int nt = 0; nt < 2; nt++) {
        *reinterpret_cast<float2*>(out + (size_t)vA  * DVEC + 8 * nt + 2 * q) =
            make_float2(zA[nt][0] * igA, zA[nt][1] * igA);
        *reinterpret_cast<float2*>(out + (size_t)vA8 * DVEC + 8 * nt + 2 * q) =
            make_float2(zA[nt][2] * i8A, zA[nt][3] * i8A);
        *reinterpret_cast<float2*>(out + (size_t)vB  * DVEC + 8 * nt + 2 * q) =
            make_float2(zB[nt][0] * igB, zB[nt][1] * igB);
        *reinterpret_cast<float2*>(out + (size_t)vB8 * DVEC + 8 * nt + 2 * q) =
            make_float2(zB[nt][2] * i8B, zB[nt][3] * i8B);
    }
}

extern "C" void kernel_launch(void* const* d_in, const int* in_sizes, int n_in,
                              void* d_out, int out_size) {
    const float* x   = (const float*)d_in[0];   // (64,8,32,32,16) f32
    const float* ref = (const float*)d_in[1];   // (64,16) f32
    float* out = (float*)d_out;

    prep_kernel<<<1, 256>>>(ref);

    const int nvec = in_sizes[0] / DVEC;        // 524288
    const int tiles = nvec / 16;                // 32768
    const int blocks = tiles / 8;               // 4096 (4 warps x 2 tiles)
    stq_kernel<<<blocks, TPB>>>(x, out);
}